// round 1
// baseline (speedup 1.0000x reference)
#include <cuda_runtime.h>
#include <math_constants.h>

// Problem constants
#define BB 8
#define TT 2048
#define CC 512
#define HH 8
#define DD 64

// Scratch (device globals — allocation-free per harness rules)
__device__ float g_q[(size_t)BB * TT * CC];
__device__ float g_k[(size_t)BB * TT * CC];
__device__ float g_v[(size_t)BB * TT * CC];
__device__ float g_y[(size_t)BB * TT * CC];

// ============================================================================
// GEMM-NT: Y[M,512] = X[M,512] * W[512,512]^T   (Y[m,n] = sum_k X[m,k]*W[n,k])
// Tiles: BM=BN=64, BK=32, 256 threads, 4x4 micro-tile per thread.
// smem tiles stored transposed [k][m] with stride 68 (pad 4) -> float4 frags,
// conflict-free reads.
// ============================================================================
__global__ __launch_bounds__(256) void gemm_nt(const float* __restrict__ X,
                                               const float* __restrict__ W,
                                               float* __restrict__ Y) {
    __shared__ float Xs[32][68];
    __shared__ float Ws[32][68];

    const int tid = threadIdx.x;
    const int tx = tid & 15;       // 0..15 -> n micro
    const int ty = tid >> 4;       // 0..15 -> m micro
    const int m0 = blockIdx.y * 64;
    const int n0 = blockIdx.x * 64;

    const int r0 = tid >> 3;           // 0..31
    const int c4 = (tid & 7) * 4;      // 0,4,...,28

    float acc[4][4] = {};

    for (int kt = 0; kt < 512; kt += 32) {
        #pragma unroll
        for (int l = 0; l < 2; ++l) {
            const int r = r0 + l * 32;   // 0..63
            float4 xv = *(const float4*)(X + (size_t)(m0 + r) * 512 + kt + c4);
            Xs[c4 + 0][r] = xv.x; Xs[c4 + 1][r] = xv.y;
            Xs[c4 + 2][r] = xv.z; Xs[c4 + 3][r] = xv.w;
            float4 wv = *(const float4*)(W + (size_t)(n0 + r) * 512 + kt + c4);
            Ws[c4 + 0][r] = wv.x; Ws[c4 + 1][r] = wv.y;
            Ws[c4 + 2][r] = wv.z; Ws[c4 + 3][r] = wv.w;
        }
        __syncthreads();

        #pragma unroll
        for (int k = 0; k < 32; ++k) {
            float4 a = *(const float4*)&Xs[k][ty * 4];
            float4 b = *(const float4*)&Ws[k][tx * 4];
            float av[4] = {a.x, a.y, a.z, a.w};
            float bv[4] = {b.x, b.y, b.z, b.w};
            #pragma unroll
            for (int i = 0; i < 4; ++i)
                #pragma unroll
                for (int j = 0; j < 4; ++j)
                    acc[i][j] = fmaf(av[i], bv[j], acc[i][j]);
        }
        __syncthreads();
    }

    #pragma unroll
    for (int i = 0; i < 4; ++i) {
        float4 o = make_float4(acc[i][0], acc[i][1], acc[i][2], acc[i][3]);
        *(float4*)(Y + (size_t)(m0 + ty * 4 + i) * 512 + n0 + tx * 4) = o;
    }
}

// ============================================================================
// Flash attention forward (causal), fp32.
// One CTA per (b, h, q-tile of 64 rows). BM=BN=64, D=64, 256 threads.
// q/k/v live in [B,T,C] layout (C = h*64 + d).
// smem: Qs[d][m] (stride 68), Ks[d][n] (stride 68), Vs[n][d], Ps[m][n].
// ============================================================================
#define FLASH_SMEM (4 * 64 * 68 * 4)

__global__ __launch_bounds__(256) void flash_fwd() {
    extern __shared__ float sm[];
    float* Qs = sm;                 // [64][68], d-major
    float* Ks = sm + 64 * 68;       // [64][68], d-major
    float* Vs = sm + 2 * 64 * 68;   // [64][68], n-major
    float* Ps = sm + 3 * 64 * 68;   // [64][68], m-major

    const int tid = threadIdx.x;
    const int tx = tid & 15;
    const int ty = tid >> 4;
    const int qt = blockIdx.x;          // 0..31
    const int h  = blockIdx.y;
    const int b  = blockIdx.z;
    const int m0 = qt * 64;

    const float* qbase = g_q + (size_t)b * TT * CC + h * 64;
    const float* kbase = g_k + (size_t)b * TT * CC + h * 64;
    const float* vbase = g_v + (size_t)b * TT * CC + h * 64;

    // Load Q tile transposed: Qs[d][m]
    for (int idx = tid; idx < 64 * 16; idx += 256) {
        const int r  = idx >> 4;
        const int c4 = (idx & 15) * 4;
        float4 v = *(const float4*)(qbase + (size_t)(m0 + r) * CC + c4);
        Qs[(c4 + 0) * 68 + r] = v.x; Qs[(c4 + 1) * 68 + r] = v.y;
        Qs[(c4 + 2) * 68 + r] = v.z; Qs[(c4 + 3) * 68 + r] = v.w;
    }

    float m_i[4], l_i[4], o[4][4];
    #pragma unroll
    for (int i = 0; i < 4; ++i) {
        m_i[i] = -CUDART_INF_F;
        l_i[i] = 0.0f;
        #pragma unroll
        for (int j = 0; j < 4; ++j) o[i][j] = 0.0f;
    }

    for (int jt = 0; jt <= qt; ++jt) {
        __syncthreads();   // protect Ks/Vs/Ps (and first-iter Qs) before overwrite
        const int n0 = jt * 64;
        // Load K transposed [d][n] and V row-major [n][d]
        for (int idx = tid; idx < 64 * 16; idx += 256) {
            const int r  = idx >> 4;
            const int c4 = (idx & 15) * 4;
            float4 kv = *(const float4*)(kbase + (size_t)(n0 + r) * CC + c4);
            Ks[(c4 + 0) * 68 + r] = kv.x; Ks[(c4 + 1) * 68 + r] = kv.y;
            Ks[(c4 + 2) * 68 + r] = kv.z; Ks[(c4 + 3) * 68 + r] = kv.w;
            float4 vv = *(const float4*)(vbase + (size_t)(n0 + r) * CC + c4);
            *(float4*)&Vs[r * 68 + c4] = vv;
        }
        __syncthreads();

        // S = Q K^T  (64x64x64)
        float s[4][4] = {};
        #pragma unroll
        for (int d = 0; d < 64; ++d) {
            float4 a = *(const float4*)&Qs[d * 68 + ty * 4];
            float4 bq = *(const float4*)&Ks[d * 68 + tx * 4];
            float av[4] = {a.x, a.y, a.z, a.w};
            float bv[4] = {bq.x, bq.y, bq.z, bq.w};
            #pragma unroll
            for (int i = 0; i < 4; ++i)
                #pragma unroll
                for (int j = 0; j < 4; ++j)
                    s[i][j] = fmaf(av[i], bv[j], s[i][j]);
        }

        // scale + causal mask (only diagonal tile needs masking)
        const float sc = 0.125f;   // 1/sqrt(64)
        if (jt == qt) {
            #pragma unroll
            for (int i = 0; i < 4; ++i)
                #pragma unroll
                for (int j = 0; j < 4; ++j) {
                    const int row = ty * 4 + i, col = tx * 4 + j;
                    s[i][j] = (col <= row) ? s[i][j] * sc : -CUDART_INF_F;
                }
        } else {
            #pragma unroll
            for (int i = 0; i < 4; ++i)
                #pragma unroll
                for (int j = 0; j < 4; ++j) s[i][j] *= sc;
        }

        // Online softmax update (row reduce across 16 tx lanes)
        #pragma unroll
        for (int i = 0; i < 4; ++i) {
            float rmax = fmaxf(fmaxf(s[i][0], s[i][1]), fmaxf(s[i][2], s[i][3]));
            #pragma unroll
            for (int off = 8; off > 0; off >>= 1)
                rmax = fmaxf(rmax, __shfl_xor_sync(0xffffffffu, rmax, off, 16));
            const float mn = fmaxf(m_i[i], rmax);
            const float corr = __expf(m_i[i] - mn);
            m_i[i] = mn;
            float rs = 0.0f;
            #pragma unroll
            for (int j = 0; j < 4; ++j) {
                s[i][j] = __expf(s[i][j] - mn);
                rs += s[i][j];
            }
            #pragma unroll
            for (int off = 8; off > 0; off >>= 1)
                rs += __shfl_xor_sync(0xffffffffu, rs, off, 16);
            l_i[i] = l_i[i] * corr + rs;
            #pragma unroll
            for (int j = 0; j < 4; ++j) o[i][j] *= corr;
        }

        // Stage P to smem
        #pragma unroll
        for (int i = 0; i < 4; ++i)
            *(float4*)&Ps[(ty * 4 + i) * 68 + tx * 4] =
                make_float4(s[i][0], s[i][1], s[i][2], s[i][3]);
        __syncthreads();

        // O += P V  (64x64x64)
        #pragma unroll
        for (int n = 0; n < 64; ++n) {
            float4 bv4 = *(const float4*)&Vs[n * 68 + tx * 4];
            float bv[4] = {bv4.x, bv4.y, bv4.z, bv4.w};
            #pragma unroll
            for (int i = 0; i < 4; ++i) {
                const float a = Ps[(ty * 4 + i) * 68 + n];
                #pragma unroll
                for (int j = 0; j < 4; ++j)
                    o[i][j] = fmaf(a, bv[j], o[i][j]);
            }
        }
    }

    // Epilogue: O / l -> g_y [B,T,C]
    float* ybase = g_y + (size_t)b * TT * CC + h * 64;
    #pragma unroll
    for (int i = 0; i < 4; ++i) {
        const float inv = 1.0f / l_i[i];
        float4 o4 = make_float4(o[i][0] * inv, o[i][1] * inv,
                                o[i][2] * inv, o[i][3] * inv);
        *(float4*)(ybase + (size_t)(m0 + ty * 4 + i) * CC + tx * 4) = o4;
    }
}

// ============================================================================
// Launch
// ============================================================================
extern "C" void kernel_launch(void* const* d_in, const int* in_sizes, int n_in,
                              void* d_out, int out_size) {
    const float* x  = (const float*)d_in[0];
    const float* Wq = (const float*)d_in[1];
    const float* Wk = (const float*)d_in[2];
    const float* Wv = (const float*)d_in[3];
    const float* Wp = (const float*)d_in[4];
    float* out = (float*)d_out;

    float *q, *k, *v, *y;
    cudaGetSymbolAddress((void**)&q, g_q);
    cudaGetSymbolAddress((void**)&k, g_k);
    cudaGetSymbolAddress((void**)&v, g_v);
    cudaGetSymbolAddress((void**)&y, g_y);

    cudaFuncSetAttribute(flash_fwd, cudaFuncAttributeMaxDynamicSharedMemorySize,
                         FLASH_SMEM);

    const dim3 gthr(256);
    const dim3 ggrid(512 / 64, (BB * TT) / 64);   // (8, 256)

    gemm_nt<<<ggrid, gthr>>>(x, Wq, q);
    gemm_nt<<<ggrid, gthr>>>(x, Wk, k);
    gemm_nt<<<ggrid, gthr>>>(x, Wv, v);

    flash_fwd<<<dim3(TT / 64, HH, BB), gthr, FLASH_SMEM>>>();

    gemm_nt<<<ggrid, gthr>>>(y, Wp, out);
}

// round 3
// speedup vs baseline: 2.8242x; 2.8242x over previous
#include <cuda_runtime.h>
#include <math_constants.h>

// Problem constants
#define BB 8
#define TT 2048
#define CC 512
#define HH 8
#define DD 64

// Scratch (device globals — allocation-free per harness rules)
__device__ float g_q[(size_t)BB * TT * CC];
__device__ float g_k[(size_t)BB * TT * CC];
__device__ float g_v[(size_t)BB * TT * CC];
__device__ float g_y[(size_t)BB * TT * CC];

// ---------------------------------------------------------------------------
// Helpers: tf32 convert + m16n8k8 tf32 MMA
// ---------------------------------------------------------------------------
__device__ __forceinline__ unsigned f2tf32(float x) {
    unsigned u;
    asm("cvt.rna.tf32.f32 %0, %1;" : "=r"(u) : "f"(x));
    return u;
}

__device__ __forceinline__ void mma_tf32(float c[4], const unsigned a[4],
                                         const unsigned b[2]) {
    asm volatile(
        "mma.sync.aligned.m16n8k8.row.col.f32.tf32.tf32.f32 "
        "{%0,%1,%2,%3}, {%4,%5,%6,%7}, {%8,%9}, {%0,%1,%2,%3};\n"
        : "+f"(c[0]), "+f"(c[1]), "+f"(c[2]), "+f"(c[3])
        : "r"(a[0]), "r"(a[1]), "r"(a[2]), "r"(a[3]), "r"(b[0]), "r"(b[1]));
}

// ---------------------------------------------------------------------------
// GEMM-NT (tf32 tensor cores): Y[M,512] = X[M,512] * W[512,512]^T
// CTA tile 128x128, BK=32, 256 threads = 8 warps in 2(m) x 4(n) grid,
// warp tile 64x32. smem stride 36 words -> conflict-free frag fetch.
// ---------------------------------------------------------------------------
__global__ __launch_bounds__(256, 2) void gemm_nt_tc(const float* __restrict__ X,
                                                     const float* __restrict__ W,
                                                     float* __restrict__ Y) {
    __shared__ unsigned Xs[128][36];
    __shared__ unsigned Ws[128][36];

    const int tid  = threadIdx.x;
    const int lane = tid & 31;
    const int warp = tid >> 5;
    const int g    = lane >> 2;      // 0..7
    const int t    = lane & 3;       // 0..3
    const int wm   = warp >> 2;      // 0..1  -> m offset 64*wm
    const int wn   = warp & 3;       // 0..3  -> n offset 32*wn
    const int m0   = blockIdx.y * 128;
    const int n0   = blockIdx.x * 128;

    const int lr = tid >> 3;            // 0..31
    const int lc = (tid & 7) * 4;       // 0,4,...,28

    float c[4][4][4];
    #pragma unroll
    for (int i = 0; i < 4; ++i)
        #pragma unroll
        for (int j = 0; j < 4; ++j)
            #pragma unroll
            for (int r = 0; r < 4; ++r) c[i][j][r] = 0.0f;

    for (int kt = 0; kt < 512; kt += 32) {
        #pragma unroll
        for (int p = 0; p < 4; ++p) {
            const int row = lr + p * 32;
            float4 xv = *(const float4*)(X + (size_t)(m0 + row) * 512 + kt + lc);
            uint4 xu = make_uint4(f2tf32(xv.x), f2tf32(xv.y), f2tf32(xv.z), f2tf32(xv.w));
            *(uint4*)&Xs[row][lc] = xu;
            float4 wv = *(const float4*)(W + (size_t)(n0 + row) * 512 + kt + lc);
            uint4 wu = make_uint4(f2tf32(wv.x), f2tf32(wv.y), f2tf32(wv.z), f2tf32(wv.w));
            *(uint4*)&Ws[row][lc] = wu;
        }
        __syncthreads();

        #pragma unroll
        for (int ks = 0; ks < 4; ++ks) {
            unsigned a[4][4], b[4][2];
            #pragma unroll
            for (int i = 0; i < 4; ++i) {
                const int r = wm * 64 + i * 16 + g;
                a[i][0] = Xs[r][ks * 8 + t];
                a[i][1] = Xs[r + 8][ks * 8 + t];
                a[i][2] = Xs[r][ks * 8 + t + 4];
                a[i][3] = Xs[r + 8][ks * 8 + t + 4];
            }
            #pragma unroll
            for (int j = 0; j < 4; ++j) {
                const int n = wn * 32 + j * 8 + g;
                b[j][0] = Ws[n][ks * 8 + t];
                b[j][1] = Ws[n][ks * 8 + t + 4];
            }
            #pragma unroll
            for (int i = 0; i < 4; ++i)
                #pragma unroll
                for (int j = 0; j < 4; ++j)
                    mma_tf32(c[i][j], a[i], b[j]);
        }
        __syncthreads();
    }

    #pragma unroll
    for (int i = 0; i < 4; ++i) {
        const int row = m0 + wm * 64 + i * 16 + g;
        #pragma unroll
        for (int j = 0; j < 4; ++j) {
            const int col = n0 + wn * 32 + j * 8 + 2 * t;
            *(float2*)(Y + (size_t)row * 512 + col)       = make_float2(c[i][j][0], c[i][j][1]);
            *(float2*)(Y + (size_t)(row + 8) * 512 + col) = make_float2(c[i][j][2], c[i][j][3]);
        }
    }
}

// ---------------------------------------------------------------------------
// Flash attention (causal) with tf32 tensor cores.
// CTA: 128 q-rows, 8 warps x 16-row strips, KV tiles of 64, D=64.
// Q fragments register-resident; K smem stride 68, V stride 72, per-warp P
// staging (stride 68, warp-private -> __syncwarp only).
// ---------------------------------------------------------------------------
#define KS_STRIDE 68
#define VS_STRIDE 72
#define PS_STRIDE 68
#define KS_WORDS (64 * KS_STRIDE)
#define VS_WORDS (64 * VS_STRIDE)
#define PS_WORDS (8 * 16 * PS_STRIDE)
#define FLASH_SMEM ((KS_WORDS + VS_WORDS + PS_WORDS) * 4)

__global__ __launch_bounds__(256, 1) void flash_fwd_tc() {
    extern __shared__ unsigned sm[];
    unsigned* Ks = sm;                     // [64][68]
    unsigned* Vs = sm + KS_WORDS;          // [64][72]
    unsigned* Ps = sm + KS_WORDS + VS_WORDS; // [8][16][68]

    const int tid  = threadIdx.x;
    const int lane = tid & 31;
    const int w    = tid >> 5;       // warp 0..7
    const int g    = lane >> 2;
    const int t    = lane & 3;
    const int qt   = gridDim.x - 1 - blockIdx.x;   // heavy tiles first
    const int h    = blockIdx.y;
    const int b    = blockIdx.z;

    const size_t headoff = (size_t)b * TT * CC + (size_t)h * DD;
    const float* qbase = g_q + headoff;
    const float* kbase = g_k + headoff;
    const float* vbase = g_v + headoff;

    const int row_min = qt * 128 + w * 16;   // first absolute q-row of this warp

    // Q fragments: rows row_min + {g, g+8}, 8 k-steps of 8 over D=64
    unsigned qa[8][4];
    {
        const float* q0 = qbase + (size_t)(row_min + g) * CC;
        const float* q1 = qbase + (size_t)(row_min + g + 8) * CC;
        #pragma unroll
        for (int ks = 0; ks < 8; ++ks) {
            qa[ks][0] = f2tf32(q0[ks * 8 + t]);
            qa[ks][1] = f2tf32(q1[ks * 8 + t]);
            qa[ks][2] = f2tf32(q0[ks * 8 + t + 4]);
            qa[ks][3] = f2tf32(q1[ks * 8 + t + 4]);
        }
    }

    float o[8][4];
    #pragma unroll
    for (int dt = 0; dt < 8; ++dt)
        #pragma unroll
        for (int r = 0; r < 4; ++r) o[dt][r] = 0.0f;
    float mrow0 = -CUDART_INF_F, mrow1 = -CUDART_INF_F;
    float lrow0 = 0.0f, lrow1 = 0.0f;

    unsigned* Pw = Ps + w * 16 * PS_STRIDE;

    const int jt_max = 2 * qt + 1;
    for (int jt = 0; jt <= jt_max; ++jt) {
        const int n0 = jt * 64;
        __syncthreads();   // previous tile's consumers done

        // Load K (stride 68) and V (stride 72), tf32-converted
        {
            const int r  = tid >> 2;            // 0..63
            const int cb = (tid & 3) * 16;      // 0,16,32,48
            const float* krow = kbase + (size_t)(n0 + r) * CC + cb;
            const float* vrow = vbase + (size_t)(n0 + r) * CC + cb;
            #pragma unroll
            for (int q4 = 0; q4 < 4; ++q4) {
                float4 kv = *(const float4*)(krow + q4 * 4);
                *(uint4*)&Ks[r * KS_STRIDE + cb + q4 * 4] =
                    make_uint4(f2tf32(kv.x), f2tf32(kv.y), f2tf32(kv.z), f2tf32(kv.w));
                float4 vv = *(const float4*)(vrow + q4 * 4);
                *(uint4*)&Vs[r * VS_STRIDE + cb + q4 * 4] =
                    make_uint4(f2tf32(vv.x), f2tf32(vv.y), f2tf32(vv.z), f2tf32(vv.w));
            }
        }
        __syncthreads();

        if (n0 <= row_min) {   // warp has work in this KV tile
            // S = Q K^T : 8 j-tiles of 8 cols
            float s[8][4];
            #pragma unroll
            for (int j = 0; j < 8; ++j)
                #pragma unroll
                for (int r = 0; r < 4; ++r) s[j][r] = 0.0f;

            #pragma unroll
            for (int ks = 0; ks < 8; ++ks) {
                #pragma unroll
                for (int j = 0; j < 8; ++j) {
                    unsigned bf[2];
                    bf[0] = Ks[(j * 8 + g) * KS_STRIDE + ks * 8 + t];
                    bf[1] = Ks[(j * 8 + g) * KS_STRIDE + ks * 8 + t + 4];
                    mma_tf32(s[j], qa[ks], bf);
                }
            }

            // scale + causal mask
            const float sc = 0.125f;
            const bool need_mask = (n0 + 63 > row_min);
            const int r0a = row_min + g;
            const int r1a = row_min + g + 8;
            #pragma unroll
            for (int j = 0; j < 8; ++j) {
                const int c0a = n0 + j * 8 + 2 * t;
                #pragma unroll
                for (int r = 0; r < 4; ++r) s[j][r] *= sc;
                if (need_mask) {
                    if (c0a     > r0a) s[j][0] = -CUDART_INF_F;
                    if (c0a + 1 > r0a) s[j][1] = -CUDART_INF_F;
                    if (c0a     > r1a) s[j][2] = -CUDART_INF_F;
                    if (c0a + 1 > r1a) s[j][3] = -CUDART_INF_F;
                }
            }

            // online softmax
            float rmax0 = -CUDART_INF_F, rmax1 = -CUDART_INF_F;
            #pragma unroll
            for (int j = 0; j < 8; ++j) {
                rmax0 = fmaxf(rmax0, fmaxf(s[j][0], s[j][1]));
                rmax1 = fmaxf(rmax1, fmaxf(s[j][2], s[j][3]));
            }
            rmax0 = fmaxf(rmax0, __shfl_xor_sync(0xffffffffu, rmax0, 1));
            rmax0 = fmaxf(rmax0, __shfl_xor_sync(0xffffffffu, rmax0, 2));
            rmax1 = fmaxf(rmax1, __shfl_xor_sync(0xffffffffu, rmax1, 1));
            rmax1 = fmaxf(rmax1, __shfl_xor_sync(0xffffffffu, rmax1, 2));

            const float mn0 = fmaxf(mrow0, rmax0);
            const float mn1 = fmaxf(mrow1, rmax1);
            const float corr0 = __expf(mrow0 - mn0);
            const float corr1 = __expf(mrow1 - mn1);
            mrow0 = mn0; mrow1 = mn1;

            float rs0 = 0.0f, rs1 = 0.0f;
            #pragma unroll
            for (int j = 0; j < 8; ++j) {
                s[j][0] = __expf(s[j][0] - mn0);
                s[j][1] = __expf(s[j][1] - mn0);
                s[j][2] = __expf(s[j][2] - mn1);
                s[j][3] = __expf(s[j][3] - mn1);
                rs0 += s[j][0] + s[j][1];
                rs1 += s[j][2] + s[j][3];
            }
            rs0 += __shfl_xor_sync(0xffffffffu, rs0, 1);
            rs0 += __shfl_xor_sync(0xffffffffu, rs0, 2);
            rs1 += __shfl_xor_sync(0xffffffffu, rs1, 1);
            rs1 += __shfl_xor_sync(0xffffffffu, rs1, 2);
            lrow0 = lrow0 * corr0 + rs0;
            lrow1 = lrow1 * corr1 + rs1;

            #pragma unroll
            for (int dt = 0; dt < 8; ++dt) {
                o[dt][0] *= corr0; o[dt][1] *= corr0;
                o[dt][2] *= corr1; o[dt][3] *= corr1;
            }

            // stage P (tf32 bits), warp-private
            __syncwarp();
            #pragma unroll
            for (int j = 0; j < 8; ++j) {
                *(uint2*)&Pw[g * PS_STRIDE + j * 8 + 2 * t] =
                    make_uint2(f2tf32(s[j][0]), f2tf32(s[j][1]));
                *(uint2*)&Pw[(g + 8) * PS_STRIDE + j * 8 + 2 * t] =
                    make_uint2(f2tf32(s[j][2]), f2tf32(s[j][3]));
            }
            __syncwarp();

            // O += P V
            #pragma unroll
            for (int ks = 0; ks < 8; ++ks) {
                unsigned a[4];
                a[0] = Pw[g * PS_STRIDE + ks * 8 + t];
                a[1] = Pw[(g + 8) * PS_STRIDE + ks * 8 + t];
                a[2] = Pw[g * PS_STRIDE + ks * 8 + t + 4];
                a[3] = Pw[(g + 8) * PS_STRIDE + ks * 8 + t + 4];
                #pragma unroll
                for (int dt = 0; dt < 8; ++dt) {
                    unsigned bf[2];
                    bf[0] = Vs[(ks * 8 + t) * VS_STRIDE + dt * 8 + g];
                    bf[1] = Vs[(ks * 8 + t + 4) * VS_STRIDE + dt * 8 + g];
                    mma_tf32(o[dt], a, bf);
                }
            }
        }
    }

    // epilogue: O / l  -> g_y [B,T,C]
    float* ybase = g_y + headoff;
    const float inv0 = 1.0f / lrow0;
    const float inv1 = 1.0f / lrow1;
    #pragma unroll
    for (int dt = 0; dt < 8; ++dt) {
        const int col = dt * 8 + 2 * t;
        *(float2*)(ybase + (size_t)(row_min + g) * CC + col) =
            make_float2(o[dt][0] * inv0, o[dt][1] * inv0);
        *(float2*)(ybase + (size_t)(row_min + g + 8) * CC + col) =
            make_float2(o[dt][2] * inv1, o[dt][3] * inv1);
    }
}

// ---------------------------------------------------------------------------
// Launch
// ---------------------------------------------------------------------------
extern "C" void kernel_launch(void* const* d_in, const int* in_sizes, int n_in,
                              void* d_out, int out_size) {
    const float* x  = (const float*)d_in[0];
    const float* Wq = (const float*)d_in[1];
    const float* Wk = (const float*)d_in[2];
    const float* Wv = (const float*)d_in[3];
    const float* Wp = (const float*)d_in[4];
    float* out = (float*)d_out;

    float *q, *k, *v, *y;
    cudaGetSymbolAddress((void**)&q, g_q);
    cudaGetSymbolAddress((void**)&k, g_k);
    cudaGetSymbolAddress((void**)&v, g_v);
    cudaGetSymbolAddress((void**)&y, g_y);

    cudaFuncSetAttribute(flash_fwd_tc, cudaFuncAttributeMaxDynamicSharedMemorySize,
                         FLASH_SMEM);

    const dim3 gthr(256);
    const dim3 ggrid(512 / 128, (BB * TT) / 128);   // (4, 128)

    gemm_nt_tc<<<ggrid, gthr>>>(x, Wq, q);
    gemm_nt_tc<<<ggrid, gthr>>>(x, Wk, k);
    gemm_nt_tc<<<ggrid, gthr>>>(x, Wv, v);

    flash_fwd_tc<<<dim3(TT / 128, HH, BB), gthr, FLASH_SMEM>>>();

    gemm_nt_tc<<<ggrid, gthr>>>(y, Wp, out);
}